// round 1
// baseline (speedup 1.0000x reference)
#include <cuda_runtime.h>

// ---------------- Problem constants ----------------
#define NBOX 8000          // 5 anchors * 40 * 40
#define NA 5
#define HW 40
#define NCLS 20
#define CHSTRIDE (HW*HW)   // 1600 floats between channels
#define STRIDEPX 8.0f      // 320 / 40
#define IOU_THR 0.5f

// rank-sort chunking
#define JC 16
#define CHUNK (NBOX/JC)    // 500
#define IGROUPS 32         // 32 * 256 = 8192 >= 8000

// NMS shared capacity per class
#define CAP 2048

// ---------------- Scratch (device globals, no allocation) ----------------
__device__ float              d_dec6[NBOX * 6];       // cx,cy,w,h,conf,cls (original index order)
__device__ unsigned long long d_key[NBOX];            // sort key: (~bits(conf))<<32 | idx
__device__ unsigned char      d_code[NBOX];           // valid ? cls : 255
__device__ int                d_partial[JC * NBOX];   // partial rank counts
__device__ int                d_ord[NBOX];            // sorted position p -> original index
__device__ int                d_clist[NCLS * NBOX];   // per-class list of sorted positions
__device__ int                d_cnt[NCLS];
__device__ unsigned char      d_keep[NBOX];           // keep flag per sorted position

// ---------------- K1: decode ----------------
__global__ void k_decode(const float* __restrict__ x, const float* __restrict__ anchors) {
    int i = blockIdx.x * blockDim.x + threadIdx.x;
    if (i >= NBOX) return;
    int a   = i / (HW * HW);
    int rem = i - a * (HW * HW);
    int gy  = rem / HW;
    int gx  = rem - gy * HW;
    int base = ((a * 25) * HW + gy) * HW + gx;

    float t0 = x[base + 0 * CHSTRIDE];
    float t1 = x[base + 1 * CHSTRIDE];
    float t2 = x[base + 2 * CHSTRIDE];
    float t3 = x[base + 3 * CHSTRIDE];
    float t4 = x[base + 4 * CHSTRIDE];

    float tx   = 1.0f / (1.0f + expf(-t0));
    float ty   = 1.0f / (1.0f + expf(-t1));
    float conf = 1.0f / (1.0f + expf(-t4));

    float aw = anchors[a * 2 + 0];
    float ah = anchors[a * 2 + 1];

    float bx = (tx + (float)gx) * STRIDEPX;
    float by = (ty + (float)gy) * STRIDEPX;
    float bw = expf(t2) * aw * STRIDEPX;
    float bh = expf(t3) * ah * STRIDEPX;

    // argmax over class logits (sigmoid monotone -> argmax on raw logits,
    // strict '>' keeps first occurrence like jnp.argmax)
    float best = x[base + 5 * CHSTRIDE];
    int bc = 0;
#pragma unroll
    for (int c = 1; c < NCLS; c++) {
        float t = x[base + (5 + c) * CHSTRIDE];
        if (t > best) { best = t; bc = c; }
    }

    d_dec6[i * 6 + 0] = bx;
    d_dec6[i * 6 + 1] = by;
    d_dec6[i * 6 + 2] = bw;
    d_dec6[i * 6 + 3] = bh;
    d_dec6[i * 6 + 4] = conf;
    d_dec6[i * 6 + 5] = (float)bc;

    // conf in (0,1) positive -> float bits monotone. Descending conf, tie -> ascending idx.
    unsigned u = __float_as_uint(conf);
    d_key[i] = ((unsigned long long)(~u) << 32) | (unsigned long long)(unsigned)i;

    // conf > 0.5  <=>  logit > 0 (exact, no sigmoid rounding risk)
    d_code[i] = (t4 > 0.0f) ? (unsigned char)bc : (unsigned char)255;
    d_keep[i] = 0;  // re-zero every launch (graph replay safe)
}

// ---------------- K2: chunked rank computation ----------------
// grid = IGROUPS * JC blocks of 256. block -> (i-group g, j-chunk c)
__global__ void k_rank() {
    __shared__ unsigned long long sk[CHUNK];
    int g = blockIdx.x / JC;
    int c = blockIdx.x - g * JC;
    for (int t = threadIdx.x; t < CHUNK; t += 256)
        sk[t] = d_key[c * CHUNK + t];
    __syncthreads();
    int i = g * 256 + threadIdx.x;
    if (i < NBOX) {
        unsigned long long my = d_key[i];
        int cnt = 0;
#pragma unroll 8
        for (int j = 0; j < CHUNK; j++)
            cnt += (sk[j] < my) ? 1 : 0;
        d_partial[c * NBOX + i] = cnt;
    }
}

// ---------------- K2b: rank -> permutation scatter ----------------
__global__ void k_scatter() {
    int i = blockIdx.x * blockDim.x + threadIdx.x;
    if (i >= NBOX) return;
    int r = 0;
#pragma unroll
    for (int c = 0; c < JC; c++) r += d_partial[c * NBOX + i];
    d_ord[r] = i;  // ranks are a permutation (keys unique via idx tiebreak)
}

// ---------------- K3: per-class ordered compaction (1 block, 1024 thr) ----------------
__global__ void k_compact() {
    __shared__ unsigned char scvc[NBOX];
    for (int p = threadIdx.x; p < NBOX; p += 1024)
        scvc[p] = d_code[d_ord[p]];
    __syncthreads();
    int w = threadIdx.x >> 5;
    int lane = threadIdx.x & 31;
    if (w < NCLS) {
        int cnt = 0;
        unsigned char target = (unsigned char)w;
        for (int p0 = 0; p0 < NBOX; p0 += 32) {
            bool m = (scvc[p0 + lane] == target);
            unsigned bal = __ballot_sync(0xffffffffu, m);
            if (m) d_clist[w * NBOX + cnt + __popc(bal & ((1u << lane) - 1u))] = p0 + lane;
            cnt += __popc(bal);
        }
        if (lane == 0) d_cnt[w] = cnt;
    }
}

// helper: load box coords for class-list slot j via global double-indirection (fallback)
__device__ __forceinline__ void load_box_g(int c, int j,
                                           float& x1, float& y1, float& x2, float& y2, float& ar) {
    int i = d_ord[d_clist[c * NBOX + j]];
    float cx = d_dec6[i * 6 + 0];
    float cy = d_dec6[i * 6 + 1];
    float w  = d_dec6[i * 6 + 2];
    float h  = d_dec6[i * 6 + 3];
    x1 = cx - 0.5f * w; y1 = cy - 0.5f * h;
    x2 = cx + 0.5f * w; y2 = cy + 0.5f * h;
    ar = fabsf((x2 - x1) * (y2 - y1));
}

// ---------------- K4: greedy NMS, one block per class ----------------
__global__ void k_nms() {
    __shared__ float sx1[CAP], sy1[CAP], sx2[CAP], sy2[CAP], sar[CAP];
    __shared__ unsigned char sk[NBOX];

    int c = blockIdx.x;
    int M = d_cnt[c];
    bool inS = (M <= CAP);

    for (int t = threadIdx.x; t < M; t += blockDim.x) {
        int i = d_ord[d_clist[c * NBOX + t]];
        float cx = d_dec6[i * 6 + 0];
        float cy = d_dec6[i * 6 + 1];
        float w  = d_dec6[i * 6 + 2];
        float h  = d_dec6[i * 6 + 3];
        float x1 = cx - 0.5f * w, y1 = cy - 0.5f * h;
        float x2 = cx + 0.5f * w, y2 = cy + 0.5f * h;
        if (inS) {
            sx1[t] = x1; sy1[t] = y1; sx2[t] = x2; sy2[t] = y2;
            sar[t] = fabsf((x2 - x1) * (y2 - y1));
        }
        sk[t] = 1;
    }
    __syncthreads();

    for (int i = 0; i < M - 1; i++) {
        __syncthreads();
        if (!sk[i]) continue;  // uniform: all threads read same shared value after barrier
        float xi1, yi1, xi2, yi2, ai;
        if (inS) { xi1 = sx1[i]; yi1 = sy1[i]; xi2 = sx2[i]; yi2 = sy2[i]; ai = sar[i]; }
        else     { load_box_g(c, i, xi1, yi1, xi2, yi2, ai); }
        for (int j = i + 1 + threadIdx.x; j < M; j += blockDim.x) {
            if (!sk[j]) continue;
            float xj1, yj1, xj2, yj2, aj;
            if (inS) { xj1 = sx1[j]; yj1 = sy1[j]; xj2 = sx2[j]; yj2 = sy2[j]; aj = sar[j]; }
            else     { load_box_g(c, j, xj1, yj1, xj2, yj2, aj); }
            float iw = fmaxf(fminf(xi2, xj2) - fmaxf(xi1, xj1), 0.0f);
            float ih = fmaxf(fminf(yi2, yj2) - fmaxf(yi1, yj1), 0.0f);
            float inter = iw * ih;
            float iou = inter / (ai + aj - inter + 1e-6f);
            if (iou >= IOU_THR) sk[j] = 0;
        }
    }
    __syncthreads();

    for (int t = threadIdx.x; t < M; t += blockDim.x)
        if (sk[t]) d_keep[d_clist[c * NBOX + t]] = 1;
}

// ---------------- K5: output gather ----------------
__global__ void k_out(float* __restrict__ out) {
    int t = blockIdx.x * blockDim.x + threadIdx.x;
    if (t >= NBOX * 6) return;
    int p = t / 6;
    int k = t - p * 6;
    out[t] = d_keep[p] ? d_dec6[d_ord[p] * 6 + k] : 0.0f;
}

// ---------------- launch ----------------
extern "C" void kernel_launch(void* const* d_in, const int* in_sizes, int n_in,
                              void* d_out, int out_size) {
    const float* x;
    const float* anchors;
    if (in_sizes[0] == 10) { anchors = (const float*)d_in[0]; x = (const float*)d_in[1]; }
    else                   { x = (const float*)d_in[0]; anchors = (const float*)d_in[1]; }
    float* out = (float*)d_out;

    k_decode <<<(NBOX + 127) / 128, 128>>>(x, anchors);
    k_rank   <<<IGROUPS * JC, 256>>>();
    k_scatter<<<(NBOX + 255) / 256, 256>>>();
    k_compact<<<1, 1024>>>();
    k_nms    <<<NCLS, 256>>>();
    k_out    <<<(NBOX * 6 + 255) / 256, 256>>>(out);
}

// round 3
// speedup vs baseline: 1.2220x; 1.2220x over previous
#include <cuda_runtime.h>

// ---------------- Problem constants ----------------
#define NBOX 8000          // 5 anchors * 40 * 40
#define HW 40
#define NCLS 20
#define CHSTRIDE (HW*HW)   // 1600 floats between channels
#define STRIDEPX 8.0f      // 320 / 40
#define IOU_THR 0.5f

// rank-sort chunking
#define JC 16
#define CHUNK (NBOX/JC)    // 500
#define IGROUPS 32         // 32 * 256 = 8192 >= 8000

#define CAP 1024           // shared-list capacity per class
#define MMASK 256          // mask-matrix fast-path capacity

// ---------------- Scratch (device globals, no allocation) ----------------
__device__ float              d_dec6[NBOX * 6];       // cx,cy,w,h,conf,cls (original index order)
__device__ unsigned long long d_key[NBOX];            // sort key: (~bits(conf))<<32 | idx
__device__ unsigned char      d_code[NBOX];           // valid ? cls : 255
__device__ int                d_partial[JC * NBOX];   // partial rank counts
__device__ int                d_ord[NBOX];            // sorted position p -> original index
__device__ unsigned char      d_keep[NBOX];           // keep flag per sorted position

// ---------------- K1: decode ----------------
__global__ void k_decode(const float* __restrict__ x, const float* __restrict__ anchors) {
    int i = blockIdx.x * blockDim.x + threadIdx.x;
    if (i >= NBOX) return;
    int a   = i / (HW * HW);
    int rem = i - a * (HW * HW);
    int gy  = rem / HW;
    int gx  = rem - gy * HW;
    int base = ((a * 25) * HW + gy) * HW + gx;

    float t0 = x[base + 0 * CHSTRIDE];
    float t1 = x[base + 1 * CHSTRIDE];
    float t2 = x[base + 2 * CHSTRIDE];
    float t3 = x[base + 3 * CHSTRIDE];
    float t4 = x[base + 4 * CHSTRIDE];

    float tx   = 1.0f / (1.0f + expf(-t0));
    float ty   = 1.0f / (1.0f + expf(-t1));
    float conf = 1.0f / (1.0f + expf(-t4));

    float aw = anchors[a * 2 + 0];
    float ah = anchors[a * 2 + 1];

    float bx = (tx + (float)gx) * STRIDEPX;
    float by = (ty + (float)gy) * STRIDEPX;
    float bw = expf(t2) * aw * STRIDEPX;
    float bh = expf(t3) * ah * STRIDEPX;

    // argmax over class logits (sigmoid monotone; '>' keeps first occurrence like jnp.argmax)
    float best = x[base + 5 * CHSTRIDE];
    int bc = 0;
#pragma unroll
    for (int c = 1; c < NCLS; c++) {
        float t = x[base + (5 + c) * CHSTRIDE];
        if (t > best) { best = t; bc = c; }
    }

    d_dec6[i * 6 + 0] = bx;
    d_dec6[i * 6 + 1] = by;
    d_dec6[i * 6 + 2] = bw;
    d_dec6[i * 6 + 3] = bh;
    d_dec6[i * 6 + 4] = conf;
    d_dec6[i * 6 + 5] = (float)bc;

    // conf in (0,1) positive -> float bits monotone. Descending conf, tie -> ascending idx.
    unsigned u = __float_as_uint(conf);
    d_key[i] = ((unsigned long long)(~u) << 32) | (unsigned long long)(unsigned)i;

    // conf > 0.5  <=>  logit > 0
    d_code[i] = (t4 > 0.0f) ? (unsigned char)bc : (unsigned char)255;
    d_keep[i] = 0;  // re-zero every launch (graph replay safe)
}

// ---------------- K2: chunked rank computation ----------------
__global__ void k_rank() {
    __shared__ unsigned long long sk[CHUNK];
    int g = blockIdx.x / JC;
    int c = blockIdx.x - g * JC;
    for (int t = threadIdx.x; t < CHUNK; t += 256)
        sk[t] = d_key[c * CHUNK + t];
    __syncthreads();
    int i = g * 256 + threadIdx.x;
    if (i < NBOX) {
        unsigned long long my = d_key[i];
        int cnt = 0;
#pragma unroll 10
        for (int j = 0; j < CHUNK; j++)
            cnt += (sk[j] < my) ? 1 : 0;
        d_partial[c * NBOX + i] = cnt;
    }
}

// ---------------- K2b: rank -> permutation scatter ----------------
__global__ void k_scatter() {
    int i = blockIdx.x * blockDim.x + threadIdx.x;
    if (i >= NBOX) return;
    int r = 0;
#pragma unroll
    for (int c = 0; c < JC; c++) r += d_partial[c * NBOX + i];
    d_ord[r] = i;  // ranks are a permutation (keys unique via idx tiebreak)
}

// helper: box coords for sorted position p (global path)
__device__ __forceinline__ void load_box_g(int p, float& x1, float& y1,
                                           float& x2, float& y2, float& ar) {
    int i = d_ord[p];
    float cx = d_dec6[i * 6 + 0];
    float cy = d_dec6[i * 6 + 1];
    float w  = d_dec6[i * 6 + 2];
    float h  = d_dec6[i * 6 + 3];
    x1 = cx - 0.5f * w; y1 = cy - 0.5f * h;
    x2 = cx + 0.5f * w; y2 = cy + 0.5f * h;
    ar = fabsf((x2 - x1) * (y2 - y1));
}

// ---------------- K3: fused compaction + NMS, one block per class ----------------
__global__ void k_nms() {
    __shared__ int   slist[CAP];                 // sorted positions of this class
    __shared__ float sx1[CAP], sy1[CAP], sx2[CAP], sy2[CAP], sar[CAP];
    __shared__ unsigned smask[MMASK * 8];        // suppression bit-matrix (fast path)
    __shared__ unsigned skw[8];                  // final keep words (fast path)
    __shared__ int   wcnt[8];
    __shared__ int   sbase;
    __shared__ unsigned char skbyte[NBOX];       // fallback only (M > CAP)

    int c    = blockIdx.x;
    int tid  = threadIdx.x;
    int w    = tid >> 5;
    int lane = tid & 31;

    // ---- stable ballot compaction of class c over sorted positions ----
    if (tid == 0) sbase = 0;
    __syncthreads();
    for (int t0 = 0; t0 < NBOX; t0 += 256) {
        int p = t0 + tid;
        bool m = (p < NBOX) && (d_code[d_ord[p]] == (unsigned char)c);
        unsigned bal = __ballot_sync(0xffffffffu, m);
        if (lane == 0) wcnt[w] = __popc(bal);
        __syncthreads();
        int off = sbase;
        for (int k = 0; k < w; k++) off += wcnt[k];
        if (m) {
            int slot = off + __popc(bal & ((1u << lane) - 1u));
            if (slot < CAP) slist[slot] = p;
        }
        __syncthreads();
        if (tid == 0) {
            int tot = 0;
            for (int k = 0; k < 8; k++) tot += wcnt[k];
            sbase += tot;
        }
        __syncthreads();
    }
    int M = sbase;
    if (M == 0) return;

    if (M <= CAP) {
        // load boxes into shared
        for (int t = tid; t < M; t += 256) {
            float x1, y1, x2, y2, ar;
            load_box_g(slist[t], x1, y1, x2, y2, ar);
            sx1[t] = x1; sy1[t] = y1; sx2[t] = x2; sy2[t] = y2; sar[t] = ar;
        }
        __syncthreads();

        if (M <= MMASK) {
            // ---- fast path: precompute suppression mask matrix, no per-pivot barriers ----
            int nw = (M + 31) >> 5;  // words per row
            for (int task = tid; task < M * 8; task += 256) {
                int i  = task >> 3;
                int wq = task & 7;
                unsigned bits = 0;
                if (wq < nw && (wq * 32 + 31) > i) {
                    float xi1 = sx1[i], yi1 = sy1[i], xi2 = sx2[i], yi2 = sy2[i], ai = sar[i];
                    int j0 = wq * 32;
                    int jend = min(j0 + 32, M);
#pragma unroll 4
                    for (int j = max(j0, i + 1); j < jend; j++) {
                        float iw = fmaxf(fminf(xi2, sx2[j]) - fmaxf(xi1, sx1[j]), 0.0f);
                        float ih = fmaxf(fminf(yi2, sy2[j]) - fmaxf(yi1, sy1[j]), 0.0f);
                        float inter = iw * ih;
                        float iou = inter / (ai + sar[j] - inter + 1e-6f);
                        if (iou >= IOU_THR) bits |= 1u << (j - j0);
                    }
                }
                smask[task] = bits;
            }
            __syncthreads();

            // serial greedy sweep, warp 0 (lanes 0..7 hold keep words)
            if (tid < 32) {
                unsigned kw = 0;
                if (lane < 8) {
                    int lo = lane * 32;
                    if (lo < M) {
                        int rem = M - lo;
                        kw = (rem >= 32) ? 0xffffffffu : ((1u << rem) - 1u);
                    }
                }
                for (int i = 0; i < M; i++) {
                    unsigned wi = __shfl_sync(0xffffffffu, kw, i >> 5);
                    if ((wi >> (i & 31)) & 1u)
                        if (lane < 8) kw &= ~smask[i * 8 + lane];
                }
                if (lane < 8) skw[lane] = kw;
            }
            __syncthreads();
            for (int t = tid; t < M; t += 256)
                if ((skw[t >> 5] >> (t & 31)) & 1u) d_keep[slist[t]] = 1;
        } else {
            // ---- mid path: pivot loop in shared (256 < M <= CAP) ----
            for (int t = tid; t < M; t += 256) skbyte[t] = 1;
            __syncthreads();
            for (int i = 0; i < M - 1; i++) {
                __syncthreads();
                if (!skbyte[i]) continue;
                float xi1 = sx1[i], yi1 = sy1[i], xi2 = sx2[i], yi2 = sy2[i], ai = sar[i];
                for (int j = i + 1 + tid; j < M; j += 256) {
                    if (!skbyte[j]) continue;
                    float iw = fmaxf(fminf(xi2, sx2[j]) - fmaxf(xi1, sx1[j]), 0.0f);
                    float ih = fmaxf(fminf(yi2, sy2[j]) - fmaxf(yi1, sy1[j]), 0.0f);
                    float inter = iw * ih;
                    float iou = inter / (ai + sar[j] - inter + 1e-6f);
                    if (iou >= IOU_THR) skbyte[j] = 0;
                }
            }
            __syncthreads();
            for (int t = tid; t < M; t += 256)
                if (skbyte[t]) d_keep[slist[t]] = 1;
        }
    } else {
        // ---- fallback (M > CAP, never expected): global pivot loop over sorted positions ----
        for (int p = tid; p < NBOX; p += 256)
            skbyte[p] = (d_code[d_ord[p]] == (unsigned char)c) ? 1 : 0;
        __syncthreads();
        for (int p = 0; p < NBOX - 1; p++) {
            __syncthreads();
            if (!skbyte[p]) continue;
            float xi1, yi1, xi2, yi2, ai;
            load_box_g(p, xi1, yi1, xi2, yi2, ai);
            for (int j = p + 1 + tid; j < NBOX; j += 256) {
                if (!skbyte[j]) continue;
                float xj1, yj1, xj2, yj2, aj;
                load_box_g(j, xj1, yj1, xj2, yj2, aj);
                float iw = fmaxf(fminf(xi2, xj2) - fmaxf(xi1, xj1), 0.0f);
                float ih = fmaxf(fminf(yi2, yj2) - fmaxf(yi1, yj1), 0.0f);
                float inter = iw * ih;
                float iou = inter / (ai + aj - inter + 1e-6f);
                if (iou >= IOU_THR) skbyte[j] = 0;
            }
        }
        __syncthreads();
        for (int p = tid; p < NBOX; p += 256)
            if (skbyte[p]) d_keep[p] = 1;
    }
}

// ---------------- K4: output gather ----------------
__global__ void k_out(float* __restrict__ out) {
    int t = blockIdx.x * blockDim.x + threadIdx.x;
    if (t >= NBOX * 6) return;
    int p = t / 6;
    int k = t - p * 6;
    out[t] = d_keep[p] ? d_dec6[d_ord[p] * 6 + k] : 0.0f;
}

// ---------------- launch ----------------
extern "C" void kernel_launch(void* const* d_in, const int* in_sizes, int n_in,
                              void* d_out, int out_size) {
    const float* x;
    const float* anchors;
    if (in_sizes[0] == 10) { anchors = (const float*)d_in[0]; x = (const float*)d_in[1]; }
    else                   { x = (const float*)d_in[0]; anchors = (const float*)d_in[1]; }
    float* out = (float*)d_out;

    k_decode <<<(NBOX + 127) / 128, 128>>>(x, anchors);
    k_rank   <<<IGROUPS * JC, 256>>>();
    k_scatter<<<(NBOX + 255) / 256, 256>>>();
    k_nms    <<<NCLS, 256>>>();
    k_out    <<<(NBOX * 6 + 255) / 256, 256>>>(out);
}

// round 4
// speedup vs baseline: 1.4132x; 1.1564x over previous
#include <cuda_runtime.h>

// ---------------- Problem constants ----------------
#define NBOX 8000          // 5 anchors * 40 * 40
#define HW 40
#define NCLS 20
#define CHSTRIDE (HW*HW)   // 1600 floats between channels
#define STRIDEPX 8.0f      // 320 / 40
#define IOU_THR 0.5f

// rank-sort chunking
#define JC 16
#define CHUNK (NBOX/JC)    // 500
#define IGROUPS 32         // 32 * 256 = 8192 >= 8000

#define CAP 1024           // shared sorted-list capacity per class
#define MMASK 256          // mask-matrix fast-path capacity

// ---------------- Scratch (device globals, no allocation) ----------------
__device__ float              d_dec6[NBOX * 6];       // cx,cy,w,h,conf,cls (original index order)
__device__ unsigned long long d_key[NBOX];            // sort key: (~bits(conf))<<32 | idx
__device__ unsigned char      d_code[NBOX];           // valid ? cls : 255 (fallback path only)
__device__ int                d_partial[JC * NBOX];   // partial rank counts
__device__ int                d_ord[NBOX];            // sorted position p -> original index
__device__ int                d_cand[NCLS * NBOX];    // per-class bucket of ranks (unordered)
__device__ int                d_cnt[NCLS];
__device__ unsigned char      d_keep[NBOX];           // keep flag per sorted position

// ---------------- K1: decode ----------------
__global__ void k_decode(const float* __restrict__ x, const float* __restrict__ anchors) {
    int i = blockIdx.x * blockDim.x + threadIdx.x;
    if (i >= NBOX) return;
    int a   = i / (HW * HW);
    int rem = i - a * (HW * HW);
    int gy  = rem / HW;
    int gx  = rem - gy * HW;
    int base = ((a * 25) * HW + gy) * HW + gx;

    float t0 = x[base + 0 * CHSTRIDE];
    float t1 = x[base + 1 * CHSTRIDE];
    float t2 = x[base + 2 * CHSTRIDE];
    float t3 = x[base + 3 * CHSTRIDE];
    float t4 = x[base + 4 * CHSTRIDE];

    float tx   = 1.0f / (1.0f + expf(-t0));
    float ty   = 1.0f / (1.0f + expf(-t1));
    float conf = 1.0f / (1.0f + expf(-t4));

    float aw = anchors[a * 2 + 0];
    float ah = anchors[a * 2 + 1];

    float bx = (tx + (float)gx) * STRIDEPX;
    float by = (ty + (float)gy) * STRIDEPX;
    float bw = expf(t2) * aw * STRIDEPX;
    float bh = expf(t3) * ah * STRIDEPX;

    // argmax over class logits (sigmoid monotone; '>' keeps first occurrence like jnp.argmax)
    float best = x[base + 5 * CHSTRIDE];
    int bc = 0;
#pragma unroll
    for (int c = 1; c < NCLS; c++) {
        float t = x[base + (5 + c) * CHSTRIDE];
        if (t > best) { best = t; bc = c; }
    }

    d_dec6[i * 6 + 0] = bx;
    d_dec6[i * 6 + 1] = by;
    d_dec6[i * 6 + 2] = bw;
    d_dec6[i * 6 + 3] = bh;
    d_dec6[i * 6 + 4] = conf;
    d_dec6[i * 6 + 5] = (float)bc;

    // conf in (0,1) positive -> float bits monotone. Descending conf, tie -> ascending idx.
    unsigned u = __float_as_uint(conf);
    d_key[i] = ((unsigned long long)(~u) << 32) | (unsigned long long)(unsigned)i;

    // conf > 0.5  <=>  logit > 0
    d_code[i] = (t4 > 0.0f) ? (unsigned char)bc : (unsigned char)255;
    d_keep[i] = 0;  // re-zero every launch (graph replay safe)
}

// ---------------- K2: chunked rank computation (+ zero class counters) ----------------
__global__ void k_rank() {
    __shared__ unsigned long long sk[CHUNK];
    if (blockIdx.x == 0 && threadIdx.x < NCLS) d_cnt[threadIdx.x] = 0;
    int g = blockIdx.x / JC;
    int c = blockIdx.x - g * JC;
    for (int t = threadIdx.x; t < CHUNK; t += 256)
        sk[t] = d_key[c * CHUNK + t];
    __syncthreads();
    int i = g * 256 + threadIdx.x;
    if (i < NBOX) {
        unsigned long long my = d_key[i];
        int cnt = 0;
#pragma unroll 10
        for (int j = 0; j < CHUNK; j++)
            cnt += (sk[j] < my) ? 1 : 0;
        d_partial[c * NBOX + i] = cnt;
    }
}

// ---------------- K2b: rank -> permutation + class-bucket append ----------------
__global__ void k_scatter() {
    int i = blockIdx.x * blockDim.x + threadIdx.x;
    if (i >= NBOX) return;
    int r = 0;
#pragma unroll
    for (int c = 0; c < JC; c++) r += d_partial[c * NBOX + i];
    d_ord[r] = i;  // ranks are a permutation (keys unique via idx tiebreak)
    unsigned char code = d_code[i];
    if (code != (unsigned char)255) {
        int slot = atomicAdd(&d_cnt[code], 1);
        if (slot < NBOX) d_cand[code * NBOX + slot] = r;   // unordered; sorted later by rank
    }
}

// helper: box coords for sorted position p (global path)
__device__ __forceinline__ void load_box_g(int p, float& x1, float& y1,
                                           float& x2, float& y2, float& ar) {
    int i = d_ord[p];
    float cx = d_dec6[i * 6 + 0];
    float cy = d_dec6[i * 6 + 1];
    float w  = d_dec6[i * 6 + 2];
    float h  = d_dec6[i * 6 + 3];
    x1 = cx - 0.5f * w; y1 = cy - 0.5f * h;
    x2 = cx + 0.5f * w; y2 = cy + 0.5f * h;
    ar = fabsf((x2 - x1) * (y2 - y1));
}

// ---------------- K3: per-class NMS (sorted bucket in shared) ----------------
__global__ void k_nms() {
    __shared__ int   skey[CAP];                  // unordered ranks
    __shared__ int   sps[CAP];                   // ranks sorted ascending (= conf desc order)
    __shared__ float sx1[CAP], sy1[CAP], sx2[CAP], sy2[CAP], sar[CAP];
    __shared__ unsigned smask[MMASK * 8];        // suppression bit-matrix (fast path)
    __shared__ unsigned skw[8];                  // final keep words (fast path)
    __shared__ unsigned char skbyte[NBOX];       // pivot-loop paths

    int c    = blockIdx.x;
    int tid  = threadIdx.x;
    int lane = tid & 31;
    int M    = d_cnt[c];
    if (M == 0) return;

    if (M <= CAP) {
        // ---- load unordered ranks, in-block rank-sort (ranks are unique ints) ----
        for (int t = tid; t < M; t += 256) skey[t] = d_cand[c * NBOX + t];
        __syncthreads();
        for (int t = tid; t < M; t += 256) {
            int k = skey[t], pos = 0;
            for (int j = 0; j < M; j++) pos += (skey[j] < k) ? 1 : 0;   // broadcast LDS
            sps[pos] = k;
        }
        __syncthreads();
        // ---- gather boxes in sorted order ----
        for (int t = tid; t < M; t += 256) {
            float x1, y1, x2, y2, ar;
            load_box_g(sps[t], x1, y1, x2, y2, ar);
            sx1[t] = x1; sy1[t] = y1; sx2[t] = x2; sy2[t] = y2; sar[t] = ar;
        }
        __syncthreads();

        if (M <= MMASK) {
            // ---- fast path: parallel suppression-mask matrix, zero barriers in fill ----
            int nw = (M + 31) >> 5;
            for (int task = tid; task < M * 8; task += 256) {
                int i  = task >> 3;
                int wq = task & 7;
                unsigned bits = 0;
                if (wq < nw && (wq * 32 + 31) > i) {
                    float xi1 = sx1[i], yi1 = sy1[i], xi2 = sx2[i], yi2 = sy2[i], ai = sar[i];
                    int j0 = wq * 32;
                    int jend = min(j0 + 32, M);
#pragma unroll 4
                    for (int j = max(j0, i + 1); j < jend; j++) {
                        float iw = fmaxf(fminf(xi2, sx2[j]) - fmaxf(xi1, sx1[j]), 0.0f);
                        float ih = fmaxf(fminf(yi2, sy2[j]) - fmaxf(yi1, sy1[j]), 0.0f);
                        float inter = iw * ih;
                        float iou = inter / (ai + sar[j] - inter + 1e-6f);
                        if (iou >= IOU_THR) bits |= 1u << (j - j0);
                    }
                }
                smask[task] = bits;
            }
            __syncthreads();

            // ---- serial greedy sweep, warp 0, skipping suppressed bits via ffs ----
            if (tid < 32) {
                unsigned kw = 0;
                if (lane < 8) {
                    int lo = lane * 32;
                    if (lo < M) {
                        int rem = M - lo;
                        kw = (rem >= 32) ? 0xffffffffu : ((1u << rem) - 1u);
                    }
                }
                for (int w = 0; w < nw; w++) {
                    unsigned active = __shfl_sync(0xffffffffu, kw, w);
                    while (active) {
                        int b = __ffs(active) - 1;
                        int i = w * 32 + b;
                        unsigned row = (lane < 8) ? smask[i * 8 + lane] : 0u;
                        kw &= ~row;                       // row has only bits j>i -> bit i survives
                        active = __shfl_sync(0xffffffffu, kw, w);
                        active &= (0xfffffffeu << b);     // only bits strictly above b
                    }
                }
                if (lane < 8) skw[lane] = kw;
            }
            __syncthreads();
            for (int t = tid; t < M; t += 256)
                if ((skw[t >> 5] >> (t & 31)) & 1u) d_keep[sps[t]] = 1;
        } else {
            // ---- mid path: pivot loop in shared (MMASK < M <= CAP) ----
            for (int t = tid; t < M; t += 256) skbyte[t] = 1;
            __syncthreads();
            for (int i = 0; i < M - 1; i++) {
                __syncthreads();
                if (!skbyte[i]) continue;
                float xi1 = sx1[i], yi1 = sy1[i], xi2 = sx2[i], yi2 = sy2[i], ai = sar[i];
                for (int j = i + 1 + tid; j < M; j += 256) {
                    if (!skbyte[j]) continue;
                    float iw = fmaxf(fminf(xi2, sx2[j]) - fmaxf(xi1, sx1[j]), 0.0f);
                    float ih = fmaxf(fminf(yi2, sy2[j]) - fmaxf(yi1, sy1[j]), 0.0f);
                    float inter = iw * ih;
                    float iou = inter / (ai + sar[j] - inter + 1e-6f);
                    if (iou >= IOU_THR) skbyte[j] = 0;
                }
            }
            __syncthreads();
            for (int t = tid; t < M; t += 256)
                if (skbyte[t]) d_keep[sps[t]] = 1;
        }
    } else {
        // ---- fallback (M > CAP, never expected): global pivot loop over sorted positions ----
        for (int p = tid; p < NBOX; p += 256)
            skbyte[p] = (d_code[d_ord[p]] == (unsigned char)c) ? 1 : 0;
        __syncthreads();
        for (int p = 0; p < NBOX - 1; p++) {
            __syncthreads();
            if (!skbyte[p]) continue;
            float xi1, yi1, xi2, yi2, ai;
            load_box_g(p, xi1, yi1, xi2, yi2, ai);
            for (int j = p + 1 + tid; j < NBOX; j += 256) {
                if (!skbyte[j]) continue;
                float xj1, yj1, xj2, yj2, aj;
                load_box_g(j, xj1, yj1, xj2, yj2, aj);
                float iw = fmaxf(fminf(xi2, xj2) - fmaxf(xi1, xj1), 0.0f);
                float ih = fmaxf(fminf(yi2, yj2) - fmaxf(yi1, yj1), 0.0f);
                float inter = iw * ih;
                float iou = inter / (ai + aj - inter + 1e-6f);
                if (iou >= IOU_THR) skbyte[j] = 0;
            }
        }
        __syncthreads();
        for (int p = tid; p < NBOX; p += 256)
            if (skbyte[p]) d_keep[p] = 1;
    }
}

// ---------------- K4: output gather ----------------
__global__ void k_out(float* __restrict__ out) {
    int t = blockIdx.x * blockDim.x + threadIdx.x;
    if (t >= NBOX * 6) return;
    int p = t / 6;
    int k = t - p * 6;
    out[t] = d_keep[p] ? d_dec6[d_ord[p] * 6 + k] : 0.0f;
}

// ---------------- launch ----------------
extern "C" void kernel_launch(void* const* d_in, const int* in_sizes, int n_in,
                              void* d_out, int out_size) {
    const float* x;
    const float* anchors;
    if (in_sizes[0] == 10) { anchors = (const float*)d_in[0]; x = (const float*)d_in[1]; }
    else                   { x = (const float*)d_in[0]; anchors = (const float*)d_in[1]; }
    float* out = (float*)d_out;

    k_decode <<<(NBOX + 127) / 128, 128>>>(x, anchors);
    k_rank   <<<IGROUPS * JC, 256>>>();
    k_scatter<<<(NBOX + 255) / 256, 256>>>();
    k_nms    <<<NCLS, 256>>>();
    k_out    <<<(NBOX * 6 + 255) / 256, 256>>>(out);
}